// round 2
// baseline (speedup 1.0000x reference)
#include <cuda_runtime.h>
#include <math.h>

// ---------------------------------------------------------------------------
// DenseCRF mean-field with permutohedral lattice filtering.
//   inputs: unary[N,21] f32, ws_bi[N,6], ws_sp[N,3], os_bi[N,6] i32 (1-based),
//           os_sp[N,3] i32, nbr_bi[6,Mbi,2] i32 (1-based, 0=pad), nbr_sp[3,Msp,2]
//   output: Q[N,21] f32
// ---------------------------------------------------------------------------

#define CC 21
static constexpr int  NPIX         = 512 * 512;
static constexpr long long VAL_BI  = (long long)(6 * NPIX + 1) * CC; // ~33.0M floats
static constexpr long long VAL_SP  = (long long)(3 * NPIX + 1) * CC; // ~16.5M floats

// Scratch (device globals; allocated at module load, not at runtime).
__device__ float g_val_a [VAL_BI];
__device__ float g_val_b [VAL_BI];
__device__ float g_val_sa[VAL_SP];
__device__ float g_val_sb[VAL_SP];
__device__ float g_Q  [(long long)NPIX * CC];
__device__ float g_bi [(long long)NPIX * CC];
__device__ float g_sp [(long long)NPIX * CC];
__device__ float g_nbi[NPIX];
__device__ float g_nsp[NPIX];

__device__ __forceinline__ float* valptr(int id) {
    switch (id) {
        case 0:  return g_val_a;
        case 1:  return g_val_b;
        case 2:  return g_val_sa;
        default: return g_val_sb;
    }
}
__device__ __forceinline__ float* normptr(int id) { return id == 0 ? g_nbi : g_nsp; }

// ---------------------------------------------------------------------------

__global__ __launch_bounds__(256) void k_zero(int vid, long long n) {
    long long i = (long long)blockIdx.x * blockDim.x + threadIdx.x;
    if (i < n) valptr(vid)[i] = 0.0f;
}

// 1-channel splat (for the normalization pass): val[os[i]] += ws[i]
__global__ __launch_bounds__(256) void k_splat1(const float* __restrict__ ws,
                                                const int* __restrict__ os,
                                                int vid, int NK) {
    int i = blockIdx.x * blockDim.x + threadIdx.x;
    if (i >= NK) return;
    atomicAdd(valptr(vid) + os[i], ws[i]);
}

// 1-channel blur pass j: dst[i] = src[i] + 0.5*(src[n0]+src[n1]); dst[0]=0
__global__ __launch_bounds__(256) void k_blur1(int did, int sid,
                                               const int* __restrict__ nbr, int M) {
    int i = blockIdx.x * blockDim.x + threadIdx.x;
    if (i > M) return;
    float*       dst = valptr(did);
    const float* src = valptr(sid);
    if (i == 0) { dst[0] = 0.0f; return; }
    int n0 = nbr[2 * (i - 1)];
    int n1 = nbr[2 * (i - 1) + 1];
    dst[i] = src[i] + 0.5f * (src[n0] + src[n1]);
}

// 1-channel slice -> norm = 1/(sqrt(alpha*sum)+1e-20)
__global__ __launch_bounds__(256) void k_slice_norm(int nid, int vid,
                                                    const float* __restrict__ ws,
                                                    const int* __restrict__ os,
                                                    int N, int K, float alpha) {
    int n = blockIdx.x * blockDim.x + threadIdx.x;
    if (n >= N) return;
    const float* val = valptr(vid);
    float s = 0.0f;
    for (int j = 0; j < K; j++) s += ws[n * K + j] * val[os[n * K + j]];
    float r = alpha * s;
    normptr(nid)[n] = 1.0f / (sqrtf(r) + 1e-20f);
}

// 21-channel splat: val[os[n,j]][c] += ws[n,j] * norm[n] * Q[n][c]
__global__ __launch_bounds__(256) void k_splat21(int vid, int nid,
                                                 const float* __restrict__ ws,
                                                 const int* __restrict__ os,
                                                 int N, int K) {
    int idx = blockIdx.x * blockDim.x + threadIdx.x;
    int total = N * K * CC;
    if (idx >= total) return;
    int c = idx % CC;
    int t = idx / CC;       // (n,j)
    int n = t / K;
    float contrib = ws[t] * normptr(nid)[n] * g_Q[(long long)n * CC + c];
    atomicAdd(valptr(vid) + (long long)os[t] * CC + c, contrib);
}

// 21-channel blur pass
__global__ __launch_bounds__(256) void k_blur21(int did, int sid,
                                                const int* __restrict__ nbr, int M) {
    long long idx   = (long long)blockIdx.x * blockDim.x + threadIdx.x;
    long long total = (long long)(M + 1) * CC;
    if (idx >= total) return;
    int r = (int)(idx / CC);
    int c = (int)(idx % CC);
    float*       dst = valptr(did);
    const float* src = valptr(sid);
    if (r == 0) { dst[idx] = 0.0f; return; }
    int i  = r - 1;
    int n0 = nbr[2 * i];
    int n1 = nbr[2 * i + 1];
    dst[idx] = src[idx] + 0.5f * (src[(long long)n0 * CC + c] + src[(long long)n1 * CC + c]);
}

// 21-channel slice: out[n][c] = alpha * norm[n] * sum_j ws[n,j]*val[os[n,j]][c]
__global__ __launch_bounds__(256) void k_slice21(int oid, int vid, int nid,
                                                 const float* __restrict__ ws,
                                                 const int* __restrict__ os,
                                                 int N, int K, float alpha) {
    int idx = blockIdx.x * blockDim.x + threadIdx.x;
    int total = N * CC;
    if (idx >= total) return;
    int n = idx / CC;
    int c = idx % CC;
    const float* val = valptr(vid);
    float s = 0.0f;
    for (int j = 0; j < K; j++)
        s += ws[n * K + j] * val[(long long)os[n * K + j] * CC + c];
    float* out = (oid == 0) ? g_bi : g_sp;
    out[idx] = alpha * s * normptr(nid)[n];
}

// softmax(-u [+ 10*bi + 3*sp]) per pixel. Writes g_Q, and d_out as well on last iter.
__global__ __launch_bounds__(256) void k_softmax(const float* __restrict__ u,
                                                 float* __restrict__ extout,
                                                 int N, int usepair, int to_ext) {
    int n = blockIdx.x * blockDim.x + threadIdx.x;
    if (n >= N) return;
    float l[CC];
    float mx = -1e30f;
    long long base = (long long)n * CC;
#pragma unroll
    for (int c = 0; c < CC; c++) {
        float v = -u[base + c];
        if (usepair) v += 10.0f * g_bi[base + c] + 3.0f * g_sp[base + c];
        l[c] = v;
        mx = fmaxf(mx, v);
    }
    float s = 0.0f;
#pragma unroll
    for (int c = 0; c < CC; c++) { float e = expf(l[c] - mx); l[c] = e; s += e; }
    float inv = 1.0f / s;
#pragma unroll
    for (int c = 0; c < CC; c++) {
        float q = l[c] * inv;
        g_Q[base + c] = q;
        if (to_ext) extout[base + c] = q;
    }
}

// ---------------------------------------------------------------------------

static inline unsigned gridFor(long long n) { return (unsigned)((n + 255) / 256); }

extern "C" void kernel_launch(void* const* d_in, const int* in_sizes, int n_in,
                              void* d_out, int out_size) {
    const float* unary  = (const float*)d_in[0];
    const float* ws_bi  = (const float*)d_in[1];
    const float* ws_sp  = (const float*)d_in[2];
    const int*   os_bi  = (const int*)  d_in[3];
    const int*   os_sp  = (const int*)  d_in[4];
    const int*   nbr_bi = (const int*)  d_in[5];
    const int*   nbr_sp = (const int*)  d_in[6];
    float*       out    = (float*)d_out;

    const int N   = in_sizes[1] / 6;
    const int Mbi = in_sizes[5] / 12;
    const int Msp = in_sizes[6] / 6;
    const float ALPHA_BI = 32.0f / 33.0f;  // 1/(1+2^-5)
    const float ALPHA_SP = 0.8f;           // 1/(1+2^-2)
    const int B = 256;

    // ---- normalization constants (C=1 lattice of ones) ----
    // bilateral norm: ping-pong buffers 0/1
    k_zero<<<gridFor(Mbi + 1), B>>>(0, (long long)Mbi + 1);
    k_splat1<<<gridFor((long long)N * 6), B>>>(ws_bi, os_bi, 0, N * 6);
    {
        int cur = 0;
        for (int j = 0; j < 6; j++) {
            k_blur1<<<gridFor(Mbi + 1), B>>>(1 - cur, cur, nbr_bi + (long long)j * Mbi * 2, Mbi);
            cur = 1 - cur;
        }
        k_slice_norm<<<gridFor(N), B>>>(0, cur, ws_bi, os_bi, N, 6, ALPHA_BI);
    }
    // spatial norm: ping-pong buffers 2/3
    k_zero<<<gridFor(Msp + 1), B>>>(2, (long long)Msp + 1);
    k_splat1<<<gridFor((long long)N * 3), B>>>(ws_sp, os_sp, 2, N * 3);
    {
        int cur = 2;
        for (int j = 0; j < 3; j++) {
            int dst = (cur == 2) ? 3 : 2;
            k_blur1<<<gridFor(Msp + 1), B>>>(dst, cur, nbr_sp + (long long)j * Msp * 2, Msp);
            cur = dst;
        }
        k_slice_norm<<<gridFor(N), B>>>(1, cur, ws_sp, os_sp, N, 3, ALPHA_SP);
    }

    // ---- initial Q = softmax(-u) ----
    k_softmax<<<gridFor(N), B>>>(unary, out, N, /*usepair=*/0, /*to_ext=*/0);

    // ---- mean-field iterations ----
    for (int it = 0; it < 5; it++) {
        int last = (it == 4);

        // bilateral filtering of Q*bi_norm
        k_zero<<<gridFor((long long)(Mbi + 1) * CC), B>>>(0, (long long)(Mbi + 1) * CC);
        k_splat21<<<gridFor((long long)N * 6 * CC), B>>>(0, 0, ws_bi, os_bi, N, 6);
        {
            int cur = 0;
            for (int j = 0; j < 6; j++) {
                k_blur21<<<gridFor((long long)(Mbi + 1) * CC), B>>>(
                    1 - cur, cur, nbr_bi + (long long)j * Mbi * 2, Mbi);
                cur = 1 - cur;
            }
            k_slice21<<<gridFor((long long)N * CC), B>>>(0, cur, 0, ws_bi, os_bi, N, 6, ALPHA_BI);
        }

        // spatial filtering of Q*sp_norm
        k_zero<<<gridFor((long long)(Msp + 1) * CC), B>>>(2, (long long)(Msp + 1) * CC);
        k_splat21<<<gridFor((long long)N * 3 * CC), B>>>(2, 1, ws_sp, os_sp, N, 3);
        {
            int cur = 2;
            for (int j = 0; j < 3; j++) {
                int dst = (cur == 2) ? 3 : 2;
                k_blur21<<<gridFor((long long)(Msp + 1) * CC), B>>>(
                    dst, cur, nbr_sp + (long long)j * Msp * 2, Msp);
                cur = dst;
            }
            k_slice21<<<gridFor((long long)N * CC), B>>>(1, cur, 1, ws_sp, os_sp, N, 3, ALPHA_SP);
        }

        // Q = softmax(-u + 10*bi + 3*sp)
        k_softmax<<<gridFor(N), B>>>(unary, out, N, /*usepair=*/1, /*to_ext=*/last);
    }
}

// round 3
// speedup vs baseline: 2.5303x; 2.5303x over previous
#include <cuda_runtime.h>
#include <math.h>

// ---------------------------------------------------------------------------
// DenseCRF mean-field with permutohedral lattice filtering (padded float4 form).
//   inputs: unary[N,21] f32, ws_bi[N,6], ws_sp[N,3], os_bi[N,6] i32 (1-based),
//           os_sp[N,3] i32, nbr_bi[6,Mbi,2] i32 (1-based, 0=pad), nbr_sp[3,Msp,2]
//   output: Q[N,21] f32
// Lattice value rows are padded 21 -> 24 floats (= 6 float4 groups) so every
// access is an aligned 16B vector op.
// ---------------------------------------------------------------------------

#define CC 21
#define GRP 6                       // float4 groups per padded row (24 floats)
static constexpr int       NPIX    = 512 * 512;
static constexpr long long ROWS_BI = 6LL * NPIX + 1;   // worst-case rows
static constexpr long long ROWS_SP = 3LL * NPIX + 1;

// Scratch (device globals; allocated at module load, not at runtime).
__device__ float4 g_bi_a[ROWS_BI * GRP];
__device__ float4 g_bi_b[ROWS_BI * GRP];
__device__ float4 g_sp_a[ROWS_SP * GRP];
__device__ float4 g_sp_b[ROWS_SP * GRP];
__device__ float4 g_Qp [(long long)NPIX * GRP];        // padded Q [N,24]
__device__ float  g_nbi[NPIX];
__device__ float  g_nsp[NPIX];

__device__ __forceinline__ float4* valptr4(int id) {
    switch (id) {
        case 0:  return g_bi_a;
        case 1:  return g_bi_b;
        case 2:  return g_sp_a;
        default: return g_sp_b;
    }
}

__device__ __forceinline__ void red_add_v4(float4* p, float a, float b, float c, float d) {
    asm volatile("red.global.add.v4.f32 [%0], {%1, %2, %3, %4};"
                 :: "l"(p), "f"(a), "f"(b), "f"(c), "f"(d) : "memory");
}

// ---------------------------------------------------------------------------

__global__ __launch_bounds__(256) void k_zero4(int vid, long long n4) {
    long long i = (long long)blockIdx.x * blockDim.x + threadIdx.x;
    if (i < n4) valptr4(vid)[i] = make_float4(0.f, 0.f, 0.f, 0.f);
}

// ---- 1-channel lattice (normalization constants); uses front of buffers ----

__global__ __launch_bounds__(256) void k_splat1(const float* __restrict__ ws,
                                                const int* __restrict__ os,
                                                int vid, int NK) {
    int i = blockIdx.x * blockDim.x + threadIdx.x;
    if (i >= NK) return;
    atomicAdd((float*)valptr4(vid) + os[i], ws[i]);
}

__global__ __launch_bounds__(256) void k_blur1(int did, int sid,
                                               const int* __restrict__ nbr, int M) {
    int i = blockIdx.x * blockDim.x + threadIdx.x;
    if (i > M) return;
    float*       dst = (float*)valptr4(did);
    const float* src = (const float*)valptr4(sid);
    if (i == 0) { dst[0] = 0.0f; return; }
    int2 nn = ((const int2*)nbr)[i - 1];
    dst[i] = src[i] + 0.5f * (src[nn.x] + src[nn.y]);
}

__global__ __launch_bounds__(256) void k_slice_norm(float* __restrict__ nrm, int vid,
                                                    const float* __restrict__ ws,
                                                    const int* __restrict__ os,
                                                    int N, int K, float alpha) {
    int n = blockIdx.x * blockDim.x + threadIdx.x;
    if (n >= N) return;
    const float* val = (const float*)valptr4(vid);
    float s = 0.0f;
    for (int j = 0; j < K; j++) s += ws[n * K + j] * val[os[n * K + j]];
    nrm[n] = 1.0f / (sqrtf(alpha * s) + 1e-20f);
}

// ---- 21(24)-channel lattice ops, float4 ----

// splat: val[os[n,j]] += ws[n,j]*norm[n]*Qp[n]   (vectorized reduction)
__global__ __launch_bounds__(256) void k_splat4(int vid, const float* __restrict__ nrm,
                                                const float* __restrict__ ws,
                                                const int* __restrict__ os,
                                                int N, int K) {
    int idx = blockIdx.x * blockDim.x + threadIdx.x;
    int total = N * K * GRP;
    if (idx >= total) return;
    int g = idx % GRP;
    int t = idx / GRP;        // (n, j)
    int n = t / K;
    float  w = ws[t] * nrm[n];
    float4 q = g_Qp[(long long)n * GRP + g];
    float4* dst = valptr4(vid) + (long long)os[t] * GRP + g;
    red_add_v4(dst, w * q.x, w * q.y, w * q.z, w * q.w);
}

__global__ __launch_bounds__(256) void k_blur4(int did, int sid,
                                               const int* __restrict__ nbr, int M) {
    long long idx = (long long)blockIdx.x * blockDim.x + threadIdx.x;
    long long total = (long long)(M + 1) * GRP;
    if (idx >= total) return;
    int r = (int)(idx / GRP);
    int g = (int)(idx % GRP);
    float4*       dst = valptr4(did);
    const float4* src = valptr4(sid);
    if (r == 0) { dst[g] = make_float4(0.f, 0.f, 0.f, 0.f); return; }
    int2 nn = ((const int2*)nbr)[r - 1];
    float4 a = src[(long long)r    * GRP + g];
    float4 b = src[(long long)nn.x * GRP + g];
    float4 c = src[(long long)nn.y * GRP + g];
    float4 o;
    o.x = a.x + 0.5f * (b.x + c.x);
    o.y = a.y + 0.5f * (b.y + c.y);
    o.z = a.z + 0.5f * (b.z + c.z);
    o.w = a.w + 0.5f * (b.w + c.w);
    dst[idx] = o;
}

// ---- fused slice(bi) + slice(sp) + softmax + Q update ----
// 8 lanes per pixel; lanes 0..5 own 4 channels each (24 padded), lanes 6,7 idle.
__global__ __launch_bounds__(256) void k_update(const float* __restrict__ u,
                                                float* __restrict__ extout,
                                                const float* __restrict__ ws_bi,
                                                const int* __restrict__ os_bi,
                                                const float* __restrict__ ws_sp,
                                                const int* __restrict__ os_sp,
                                                int N, int usepair, int to_ext,
                                                int bi_vid, int sp_vid,
                                                float cb, float cs) {
    int tid = blockIdx.x * blockDim.x + threadIdx.x;
    int n = tid >> 3;
    int g = tid & 7;
    if (n >= N) return;           // N*8 divisible by 256: never partial

    float l0 = -1e30f, l1 = -1e30f, l2 = -1e30f, l3 = -1e30f;
    if (g < GRP) {
        float4 acc = make_float4(0.f, 0.f, 0.f, 0.f);
        if (usepair) {
            const float4* vb = valptr4(bi_vid);
            float pb = cb * g_nbi[n];
#pragma unroll
            for (int j = 0; j < 6; j++) {
                float w = ws_bi[n * 6 + j] * pb;
                float4 v = vb[(long long)os_bi[n * 6 + j] * GRP + g];
                acc.x += w * v.x; acc.y += w * v.y; acc.z += w * v.z; acc.w += w * v.w;
            }
            const float4* vs = valptr4(sp_vid);
            float ps = cs * g_nsp[n];
#pragma unroll
            for (int j = 0; j < 3; j++) {
                float w = ws_sp[n * 3 + j] * ps;
                float4 v = vs[(long long)os_sp[n * 3 + j] * GRP + g];
                acc.x += w * v.x; acc.y += w * v.y; acc.z += w * v.z; acc.w += w * v.w;
            }
        }
        long long ub = (long long)n * CC + g * 4;
        int c0 = g * 4;
        l0 = (c0 + 0 < CC) ? (acc.x - u[ub + 0]) : -1e30f;
        l1 = (c0 + 1 < CC) ? (acc.y - u[ub + 1]) : -1e30f;
        l2 = (c0 + 2 < CC) ? (acc.z - u[ub + 2]) : -1e30f;
        l3 = (c0 + 3 < CC) ? (acc.w - u[ub + 3]) : -1e30f;
    }

    // softmax over 24 lanes' channels within the 8-lane group
    float mx = fmaxf(fmaxf(l0, l1), fmaxf(l2, l3));
#pragma unroll
    for (int d = 1; d < 8; d <<= 1)
        mx = fmaxf(mx, __shfl_xor_sync(0xffffffffu, mx, d, 8));

    float e0 = expf(l0 - mx), e1 = expf(l1 - mx), e2 = expf(l2 - mx), e3 = expf(l3 - mx);
    float s = e0 + e1 + e2 + e3;
#pragma unroll
    for (int d = 1; d < 8; d <<= 1)
        s += __shfl_xor_sync(0xffffffffu, s, d, 8);
    float inv = 1.0f / s;

    if (g < GRP) {
        float4 q = make_float4(e0 * inv, e1 * inv, e2 * inv, e3 * inv);
        g_Qp[(long long)n * GRP + g] = q;   // pads naturally 0 (e = 0)
        if (to_ext) {
            long long ob = (long long)n * CC + g * 4;
            int c0 = g * 4;
            if (c0 + 0 < CC) extout[ob + 0] = q.x;
            if (c0 + 1 < CC) extout[ob + 1] = q.y;
            if (c0 + 2 < CC) extout[ob + 2] = q.z;
            if (c0 + 3 < CC) extout[ob + 3] = q.w;
        }
    }
}

// ---------------------------------------------------------------------------

static inline unsigned gridFor(long long n) { return (unsigned)((n + 255) / 256); }

extern "C" void kernel_launch(void* const* d_in, const int* in_sizes, int n_in,
                              void* d_out, int out_size) {
    const float* unary  = (const float*)d_in[0];
    const float* ws_bi  = (const float*)d_in[1];
    const float* ws_sp  = (const float*)d_in[2];
    const int*   os_bi  = (const int*)  d_in[3];
    const int*   os_sp  = (const int*)  d_in[4];
    const int*   nbr_bi = (const int*)  d_in[5];
    const int*   nbr_sp = (const int*)  d_in[6];
    float*       out    = (float*)d_out;

    const int N   = in_sizes[1] / 6;
    const int Mbi = in_sizes[5] / 12;
    const int Msp = in_sizes[6] / 6;
    const float ALPHA_BI = 32.0f / 33.0f;  // 1/(1+2^-5)
    const float ALPHA_SP = 0.8f;           // 1/(1+2^-2)
    const float CB = 10.0f * ALPHA_BI;     // bilateral compat folded with alpha
    const float CS = 3.0f  * ALPHA_SP;
    const int B = 256;

    float* nbi = nullptr; float* nsp = nullptr; // device-symbol addresses not needed:
    // norm arrays are passed via their device-global identity inside kernels; for
    // k_slice_norm we need raw pointers — obtain once (host API allowed, no alloc).
    static float* s_nbi = nullptr; static float* s_nsp = nullptr;
    if (!s_nbi) { cudaGetSymbolAddress((void**)&s_nbi, g_nbi); cudaGetSymbolAddress((void**)&s_nsp, g_nsp); }
    nbi = s_nbi; nsp = s_nsp;

    // ---- normalization constants (C=1 lattices of ones) ----
    k_zero4<<<gridFor((Mbi + 4) / 4), B>>>(0, (long long)(Mbi + 4) / 4);
    k_splat1<<<gridFor((long long)N * 6), B>>>(ws_bi, os_bi, 0, N * 6);
    {
        int cur = 0;
        for (int j = 0; j < 6; j++) {
            k_blur1<<<gridFor(Mbi + 1), B>>>(1 - cur, cur, nbr_bi + (long long)j * Mbi * 2, Mbi);
            cur = 1 - cur;
        }
        k_slice_norm<<<gridFor(N), B>>>(nbi, cur, ws_bi, os_bi, N, 6, ALPHA_BI);
    }
    k_zero4<<<gridFor((Msp + 4) / 4), B>>>(2, (long long)(Msp + 4) / 4);
    k_splat1<<<gridFor((long long)N * 3), B>>>(ws_sp, os_sp, 2, N * 3);
    {
        int cur = 2;
        for (int j = 0; j < 3; j++) {
            int dst = (cur == 2) ? 3 : 2;
            k_blur1<<<gridFor(Msp + 1), B>>>(dst, cur, nbr_sp + (long long)j * Msp * 2, Msp);
            cur = dst;
        }
        k_slice_norm<<<gridFor(N), B>>>(nsp, cur, ws_sp, os_sp, N, 3, ALPHA_SP);
    }

    // ---- initial Q = softmax(-u) ----
    k_update<<<gridFor((long long)N * 8), B>>>(unary, out, ws_bi, os_bi, ws_sp, os_sp,
                                               N, /*usepair=*/0, /*to_ext=*/0, 0, 3, CB, CS);

    // ---- mean-field iterations ----
    for (int it = 0; it < 5; it++) {
        int last = (it == 4);

        // bilateral filtering of Q*bi_norm (buffers 0/1)
        k_zero4<<<gridFor((long long)(Mbi + 1) * GRP), B>>>(0, (long long)(Mbi + 1) * GRP);
        k_splat4<<<gridFor((long long)N * 6 * GRP), B>>>(0, nbi, ws_bi, os_bi, N, 6);
        int cur_bi = 0;
        for (int j = 0; j < 6; j++) {
            k_blur4<<<gridFor((long long)(Mbi + 1) * GRP), B>>>(
                1 - cur_bi, cur_bi, nbr_bi + (long long)j * Mbi * 2, Mbi);
            cur_bi = 1 - cur_bi;
        }

        // spatial filtering of Q*sp_norm (buffers 2/3)
        k_zero4<<<gridFor((long long)(Msp + 1) * GRP), B>>>(2, (long long)(Msp + 1) * GRP);
        k_splat4<<<gridFor((long long)N * 3 * GRP), B>>>(2, nsp, ws_sp, os_sp, N, 3);
        int cur_sp = 2;
        for (int j = 0; j < 3; j++) {
            int dst = (cur_sp == 2) ? 3 : 2;
            k_blur4<<<gridFor((long long)(Msp + 1) * GRP), B>>>(
                dst, cur_sp, nbr_sp + (long long)j * Msp * 2, Msp);
            cur_sp = dst;
        }

        // fused slice + slice + softmax -> Q (and d_out on last iter)
        k_update<<<gridFor((long long)N * 8), B>>>(unary, out, ws_bi, os_bi, ws_sp, os_sp,
                                                   N, /*usepair=*/1, /*to_ext=*/last,
                                                   cur_bi, cur_sp, CB, CS);
    }
}

// round 5
// speedup vs baseline: 3.2078x; 1.2677x over previous
#include <cuda_runtime.h>
#include <math.h>

// ---------------------------------------------------------------------------
// DenseCRF mean-field with permutohedral lattice filtering.
// Padded float4 rows (21 -> 24 ch), fused update+splat, merged bi/sp launches.
// ---------------------------------------------------------------------------

#define CC 21
#define GRP 6                       // float4 groups per padded row (24 floats)
static constexpr int       NPIX    = 512 * 512;
static constexpr long long ROWS_BI = 6LL * NPIX + 1;   // worst-case rows
static constexpr long long ROWS_SP = 3LL * NPIX + 1;

// Scratch (device globals; allocated at module load, not at runtime).
__device__ float4 g_bi_a[ROWS_BI * GRP];
__device__ float4 g_bi_b[ROWS_BI * GRP];
__device__ float4 g_sp_a[ROWS_SP * GRP];
__device__ float4 g_sp_b[ROWS_SP * GRP];
__device__ float  g_nbi[NPIX];
__device__ float  g_nsp[NPIX];

__device__ __forceinline__ float4* valptr4(int id) {
    switch (id) {
        case 0:  return g_bi_a;
        case 1:  return g_bi_b;
        case 2:  return g_sp_a;
        default: return g_sp_b;
    }
}

__device__ __forceinline__ void red_add_v4(float4* p, float a, float b, float c, float d) {
    asm volatile("red.global.add.v4.f32 [%0], {%1, %2, %3, %4};"
                 :: "l"(p), "f"(a), "f"(b), "f"(c), "f"(d) : "memory");
}

// ---------------------------------------------------------------------------

// zero two regions (float4 counts) in one launch
__global__ __launch_bounds__(256) void k_zero2(int ida, long long na,
                                               int idb, long long nb) {
    long long i = (long long)blockIdx.x * blockDim.x + threadIdx.x;
    if (i >= na + nb) return;
    if (i < na) valptr4(ida)[i]      = make_float4(0.f, 0.f, 0.f, 0.f);
    else        valptr4(idb)[i - na] = make_float4(0.f, 0.f, 0.f, 0.f);
}

// ---- 1-channel norm chain (front of buffers), bi+sp merged ----

__global__ __launch_bounds__(256) void k_splat1_both(const float* __restrict__ ws_bi,
                                                     const int* __restrict__ os_bi, int N6,
                                                     const float* __restrict__ ws_sp,
                                                     const int* __restrict__ os_sp, int N3) {
    int i = blockIdx.x * blockDim.x + threadIdx.x;
    if (i >= N6 + N3) return;
    if (i < N6) atomicAdd((float*)valptr4(0) + os_bi[i], ws_bi[i]);
    else { int j = i - N6; atomicAdd((float*)valptr4(2) + os_sp[j], ws_sp[j]); }
}

__global__ __launch_bounds__(256) void k_blur1_both(int bd, int bs,
                                                    const int* __restrict__ nbr_b, int Mb,
                                                    int sd, int ss,
                                                    const int* __restrict__ nbr_s, int Ms,
                                                    int hassp) {
    int nb = Mb + 1;
    int ns = hassp ? (Ms + 1) : 0;
    int i = blockIdx.x * blockDim.x + threadIdx.x;
    if (i >= nb + ns) return;
    int did, sid; const int* nbr; int r;
    if (i < nb) { did = bd; sid = bs; nbr = nbr_b; r = i; }
    else        { did = sd; sid = ss; nbr = nbr_s; r = i - nb; }
    float*       dst = (float*)valptr4(did);
    const float* src = (const float*)valptr4(sid);
    if (r == 0) { dst[0] = 0.0f; return; }
    int2 nn = ((const int2*)nbr)[r - 1];
    dst[r] = src[r] + 0.5f * (src[nn.x] + src[nn.y]);
}

__global__ __launch_bounds__(256) void k_norm_both(int bvid, int svid,
                                                   const float* __restrict__ ws_bi,
                                                   const int* __restrict__ os_bi,
                                                   const float* __restrict__ ws_sp,
                                                   const int* __restrict__ os_sp,
                                                   int N, float a_bi, float a_sp) {
    int n = blockIdx.x * blockDim.x + threadIdx.x;
    if (n >= N) return;
    const float* vb = (const float*)valptr4(bvid);
    float s = 0.0f;
#pragma unroll
    for (int j = 0; j < 6; j++) s += ws_bi[n * 6 + j] * vb[os_bi[n * 6 + j]];
    g_nbi[n] = 1.0f / (sqrtf(a_bi * s) + 1e-20f);
    const float* vs = (const float*)valptr4(svid);
    float t = 0.0f;
#pragma unroll
    for (int j = 0; j < 3; j++) t += ws_sp[n * 3 + j] * vs[os_sp[n * 3 + j]];
    g_nsp[n] = 1.0f / (sqrtf(a_sp * t) + 1e-20f);
}

// ---- 21(24)-channel blur, bi+sp merged (sp only rides on passes 0..2) ----

__global__ __launch_bounds__(256) void k_blur4_both(int bd, int bs,
                                                    const int* __restrict__ nbr_b, int Mb,
                                                    int sd, int ss,
                                                    const int* __restrict__ nbr_s, int Ms,
                                                    int hassp) {
    long long nb4 = (long long)(Mb + 1) * GRP;
    long long ns4 = hassp ? (long long)(Ms + 1) * GRP : 0;
    long long idx = (long long)blockIdx.x * blockDim.x + threadIdx.x;
    if (idx >= nb4 + ns4) return;
    int did, sid; const int* nbr; long long rel;
    if (idx < nb4) { did = bd; sid = bs; nbr = nbr_b; rel = idx; }
    else           { did = sd; sid = ss; nbr = nbr_s; rel = idx - nb4; }
    int r = (int)(rel / GRP);
    int g = (int)(rel % GRP);
    float4*       dst = valptr4(did);
    const float4* src = valptr4(sid);
    if (r == 0) { dst[g] = make_float4(0.f, 0.f, 0.f, 0.f); return; }
    int2 nn = ((const int2*)nbr)[r - 1];
    float4 a = src[(long long)r    * GRP + g];
    float4 b = src[(long long)nn.x * GRP + g];
    float4 c = src[(long long)nn.y * GRP + g];
    float4 o;
    o.x = a.x + 0.5f * (b.x + c.x);
    o.y = a.y + 0.5f * (b.y + c.y);
    o.z = a.z + 0.5f * (b.z + c.z);
    o.w = a.w + 0.5f * (b.w + c.w);
    dst[rel + (idx < nb4 ? 0 : 0)] = o;   // rel-indexed into dst buffer
}

// ---- fused slice(bi)+slice(sp)+softmax+Q (+splat of new Q into next buffers) ----
// 8 lanes per pixel; lanes 0..5 own 4 channels each (24 padded), lanes 6,7 idle.
__global__ __launch_bounds__(256) void k_update_splat(
        const float* __restrict__ u, float* __restrict__ extout,
        const float* __restrict__ ws_bi, const int* __restrict__ os_bi,
        const float* __restrict__ ws_sp, const int* __restrict__ os_sp,
        int N, int usepair, int to_ext, int do_splat,
        int rd_bi, int rd_sp, int wr_bi, int wr_sp, float cb, float cs) {
    int tid = blockIdx.x * blockDim.x + threadIdx.x;
    int n = tid >> 3;
    int g = tid & 7;
    if (n >= N) return;

    float nb = g_nbi[n];
    float ns = g_nsp[n];
    float wbj[6]; int obj[6];
    float wsj[3]; int osj[3];
#pragma unroll
    for (int j = 0; j < 6; j++) { wbj[j] = ws_bi[n * 6 + j]; obj[j] = os_bi[n * 6 + j]; }
#pragma unroll
    for (int j = 0; j < 3; j++) { wsj[j] = ws_sp[n * 3 + j]; osj[j] = os_sp[n * 3 + j]; }

    float l0 = -1e30f, l1 = -1e30f, l2 = -1e30f, l3 = -1e30f;
    if (g < GRP) {
        float4 acc = make_float4(0.f, 0.f, 0.f, 0.f);
        if (usepair) {
            const float4* vb = valptr4(rd_bi);
            float pb = cb * nb;
#pragma unroll
            for (int j = 0; j < 6; j++) {
                float w = wbj[j] * pb;
                float4 v = vb[(long long)obj[j] * GRP + g];
                acc.x += w * v.x; acc.y += w * v.y; acc.z += w * v.z; acc.w += w * v.w;
            }
            const float4* vs = valptr4(rd_sp);
            float ps = cs * ns;
#pragma unroll
            for (int j = 0; j < 3; j++) {
                float w = wsj[j] * ps;
                float4 v = vs[(long long)osj[j] * GRP + g];
                acc.x += w * v.x; acc.y += w * v.y; acc.z += w * v.z; acc.w += w * v.w;
            }
        }
        long long ub = (long long)n * CC + g * 4;
        int c0 = g * 4;
        l0 = (c0 + 0 < CC) ? (acc.x - u[ub + 0]) : -1e30f;
        l1 = (c0 + 1 < CC) ? (acc.y - u[ub + 1]) : -1e30f;
        l2 = (c0 + 2 < CC) ? (acc.z - u[ub + 2]) : -1e30f;
        l3 = (c0 + 3 < CC) ? (acc.w - u[ub + 3]) : -1e30f;
    }

    // softmax across the 8-lane group (24 padded channels, pads -> 0)
    float mx = fmaxf(fmaxf(l0, l1), fmaxf(l2, l3));
#pragma unroll
    for (int d = 1; d < 8; d <<= 1)
        mx = fmaxf(mx, __shfl_xor_sync(0xffffffffu, mx, d, 8));
    float e0 = expf(l0 - mx), e1 = expf(l1 - mx), e2 = expf(l2 - mx), e3 = expf(l3 - mx);
    float s = e0 + e1 + e2 + e3;
#pragma unroll
    for (int d = 1; d < 8; d <<= 1)
        s += __shfl_xor_sync(0xffffffffu, s, d, 8);
    float inv = 1.0f / s;

    if (g < GRP) {
        float4 q = make_float4(e0 * inv, e1 * inv, e2 * inv, e3 * inv);
        if (to_ext) {
            long long ob = (long long)n * CC + g * 4;
            int c0 = g * 4;
            if (c0 + 0 < CC) extout[ob + 0] = q.x;
            if (c0 + 1 < CC) extout[ob + 1] = q.y;
            if (c0 + 2 < CC) extout[ob + 2] = q.z;
            if (c0 + 3 < CC) extout[ob + 3] = q.w;
        }
        if (do_splat) {
            float4* vb = valptr4(wr_bi);
#pragma unroll
            for (int j = 0; j < 6; j++) {
                float w = wbj[j] * nb;
                red_add_v4(vb + (long long)obj[j] * GRP + g,
                           w * q.x, w * q.y, w * q.z, w * q.w);
            }
            float4* vs = valptr4(wr_sp);
#pragma unroll
            for (int j = 0; j < 3; j++) {
                float w = wsj[j] * ns;
                red_add_v4(vs + (long long)osj[j] * GRP + g,
                           w * q.x, w * q.y, w * q.z, w * q.w);
            }
        }
    }
}

// ---------------------------------------------------------------------------

static inline unsigned gridFor(long long n) { return (unsigned)((n + 255) / 256); }

extern "C" void kernel_launch(void* const* d_in, const int* in_sizes, int n_in,
                              void* d_out, int out_size) {
    const float* unary  = (const float*)d_in[0];
    const float* ws_bi  = (const float*)d_in[1];
    const float* ws_sp  = (const float*)d_in[2];
    const int*   os_bi  = (const int*)  d_in[3];
    const int*   os_sp  = (const int*)  d_in[4];
    const int*   nbr_bi = (const int*)  d_in[5];
    const int*   nbr_sp = (const int*)  d_in[6];
    float*       out    = (float*)d_out;

    const int N   = in_sizes[1] / 6;
    const int Mbi = in_sizes[5] / 12;
    const int Msp = in_sizes[6] / 6;
    const float ALPHA_BI = 32.0f / 33.0f;  // 1/(1+2^-5)
    const float ALPHA_SP = 0.8f;           // 1/(1+2^-2)
    const float CB = 10.0f * ALPHA_BI;
    const float CS = 3.0f  * ALPHA_SP;
    const int B = 256;

    const long long NB4 = (long long)(Mbi + 1) * GRP;   // bi rows in float4s
    const long long NS4 = (long long)(Msp + 1) * GRP;   // sp rows in float4s

    // ---- normalization constants (1-channel lattices of ones), merged ----
    k_zero2<<<gridFor((Mbi + 4) / 4 + (Msp + 4) / 4), B>>>(
        0, (long long)(Mbi + 4) / 4, 2, (long long)(Msp + 4) / 4);
    k_splat1_both<<<gridFor((long long)N * 9), B>>>(ws_bi, os_bi, N * 6, ws_sp, os_sp, N * 3);
    {
        int cb_ = 0, cs_ = 2;
        for (int j = 0; j < 6; j++) {
            int hassp = (j < 3);
            int bd = 1 - cb_;
            int sd = (cs_ == 2) ? 3 : 2;
            long long tot = (Mbi + 1) + (hassp ? (Msp + 1) : 0);
            k_blur1_both<<<gridFor(tot), B>>>(bd, cb_, nbr_bi + (long long)j * Mbi * 2, Mbi,
                                              sd, cs_, nbr_sp + (long long)j * Msp * 2, Msp, hassp);
            cb_ = bd;
            if (hassp) cs_ = sd;
        }
        // bi final in 0, sp final in 3
        k_norm_both<<<gridFor(N), B>>>(cb_, cs_, ws_bi, os_bi, ws_sp, os_sp, N, ALPHA_BI, ALPHA_SP);
    }

    // ---- initial Q = softmax(-u), splat directly into buffers (bi s_bi, sp 2) ----
    int s_bi = 0;
    k_zero2<<<gridFor(NB4 + NS4), B>>>(s_bi, NB4, 2, NS4);
    k_update_splat<<<gridFor((long long)N * 8), B>>>(
        unary, out, ws_bi, os_bi, ws_sp, os_sp, N,
        /*usepair=*/0, /*to_ext=*/0, /*do_splat=*/1,
        0, 0, /*wr_bi=*/s_bi, /*wr_sp=*/2, CB, CS);

    // ---- mean-field iterations ----
    for (int it = 0; it < 5; it++) {
        // blur: bi src = s_bi (6 passes), sp src = 2 (3 passes, ride along on 0..2)
        int cb_ = s_bi, cs_ = 2;
        for (int j = 0; j < 6; j++) {
            int hassp = (j < 3);
            int bd = 1 - cb_;
            int sd = (cs_ == 2) ? 3 : 2;
            long long tot = NB4 + (hassp ? NS4 : 0);
            k_blur4_both<<<gridFor(tot), B>>>(bd, cb_, nbr_bi + (long long)j * Mbi * 2, Mbi,
                                              sd, cs_, nbr_sp + (long long)j * Msp * 2, Msp, hassp);
            cb_ = bd;
            if (hassp) cs_ = sd;
        }
        int f_bi = cb_;          // == s_bi (even # of flips)
        int o_bi = 1 - f_bi;     // free buffer (last read by pass 5)
        // sp final always in 3; sp buffer 2 free (last read by pass 2)

        if (it < 4) {
            k_zero2<<<gridFor(NB4 + NS4), B>>>(o_bi, NB4, 2, NS4);
            k_update_splat<<<gridFor((long long)N * 8), B>>>(
                unary, out, ws_bi, os_bi, ws_sp, os_sp, N,
                /*usepair=*/1, /*to_ext=*/0, /*do_splat=*/1,
                f_bi, 3, /*wr_bi=*/o_bi, /*wr_sp=*/2, CB, CS);
            s_bi = o_bi;
        } else {
            k_update_splat<<<gridFor((long long)N * 8), B>>>(
                unary, out, ws_bi, os_bi, ws_sp, os_sp, N,
                /*usepair=*/1, /*to_ext=*/1, /*do_splat=*/0,
                f_bi, 3, 0, 2, CB, CS);
        }
    }
}